// round 1
// baseline (speedup 1.0000x reference)
#include <cuda_runtime.h>
#include <cuda_bf16.h>
#include <mma.h>
#include <cstdint>

using namespace nvcuda;

// ---------------- Problem constants ----------------
#define D_MODEL 1024
#define NHEAD   16
#define DHEAD   64
#define DFF     4096
#define BB      2
#define SS      2048
#define RR      25
#define WW      51          // 2R+1
#define KCLIP   5
#define NTOK    (BB * SS)   // 4096

// ---------------- Scratch (static device memory; no allocations) ----------------
__device__ float g_qkv[(size_t)NTOK * 3 * D_MODEL]; // Q|K|V per token, stride 3072
__device__ float g_z  [(size_t)NTOK * D_MODEL];     // attention output (pre out-proj)
__device__ float g_c1 [(size_t)NTOK * D_MODEL];     // gemm scratch / residual sums
__device__ float g_x1 [(size_t)NTOK * D_MODEL];     // post-LN1 activations
__device__ float g_c2 [(size_t)NTOK * DFF];         // FFN hidden (in-place relu)

// ---------------- TF32 wmma GEMM: C[M,N] = A[M,K] @ B[N,K]^T ----------------
// A row-major (lda=K), B row-major (ldb=K), C row-major with ldc param.
#define BM 128
#define BN 128
#define BK 32
#define LDT 36   // padded shared ld (floats); 144B, multiple of 16B

__global__ __launch_bounds__(256) void gemm_tf32(
    const float* __restrict__ A, const float* __restrict__ B,
    float* __restrict__ C, int M, int N, int K, int ldc)
{
    __shared__ __align__(16) float As[BM][LDT];
    __shared__ __align__(16) float Bs[BN][LDT];

    const int tid  = threadIdx.x;
    const int bm   = blockIdx.y * BM;
    const int bn   = blockIdx.x * BN;
    const int warp = tid >> 5;
    const int wm   = (warp & 3) * 32;   // 4 warps along M (32 rows each)
    const int wn   = (warp >> 2) * 64;  // 2 warps along N (64 cols each)

    wmma::fragment<wmma::accumulator, 16, 16, 8, float> acc[2][4];
#pragma unroll
    for (int i = 0; i < 2; i++)
#pragma unroll
        for (int j = 0; j < 4; j++) wmma::fill_fragment(acc[i][j], 0.0f);

    for (int k0 = 0; k0 < K; k0 += BK) {
        // Load 128x32 fp32 tiles for A and B (float4 vectorized, coalesced)
#pragma unroll
        for (int t = 0; t < 4; t++) {
            int idx = tid + t * 256;           // 0..1023
            int r = idx >> 3, q = idx & 7;     // row, float4-quad
            *(float4*)(&As[r][q * 4]) =
                *(const float4*)(A + (size_t)(bm + r) * K + k0 + q * 4);
            *(float4*)(&Bs[r][q * 4]) =
                *(const float4*)(B + (size_t)(bn + r) * K + k0 + q * 4);
        }
        __syncthreads();

#pragma unroll
        for (int kk = 0; kk < BK; kk += 8) {
            wmma::fragment<wmma::matrix_a, 16, 16, 8, wmma::precision::tf32, wmma::row_major> af[2];
            wmma::fragment<wmma::matrix_b, 16, 16, 8, wmma::precision::tf32, wmma::col_major> bf[4];
#pragma unroll
            for (int i = 0; i < 2; i++) {
                wmma::load_matrix_sync(af[i], &As[wm + i * 16][kk], LDT);
#pragma unroll
                for (int t = 0; t < af[i].num_elements; t++)
                    af[i].x[t] = wmma::__float_to_tf32(af[i].x[t]);
            }
#pragma unroll
            for (int j = 0; j < 4; j++) {
                wmma::load_matrix_sync(bf[j], &Bs[wn + j * 16][kk], LDT);
#pragma unroll
                for (int t = 0; t < bf[j].num_elements; t++)
                    bf[j].x[t] = wmma::__float_to_tf32(bf[j].x[t]);
            }
#pragma unroll
            for (int i = 0; i < 2; i++)
#pragma unroll
                for (int j = 0; j < 4; j++)
                    wmma::mma_sync(acc[i][j], af[i], bf[j], acc[i][j]);
        }
        __syncthreads();
    }

#pragma unroll
    for (int i = 0; i < 2; i++)
#pragma unroll
        for (int j = 0; j < 4; j++)
            wmma::store_matrix_sync(
                &C[(size_t)(bm + wm + i * 16) * ldc + bn + wn + j * 16],
                acc[i][j], ldc, wmma::mem_row_major);
}

// ---------------- Windowed relative attention ----------------
// One CTA: 64 queries of one (batch, head). K/V window + Q + rel in smem (stride 65).
#define TS 64
#define KROWS (TS + 2 * RR)   // 114
#define ATTN_SMEM (((KROWS * 65) * 2 + TS * 65 + 11 * 65) * 4)  // 78780 B

__global__ __launch_bounds__(256) void attn_kernel(
    const float* __restrict__ qkv,
    const float* __restrict__ bq, const float* __restrict__ bk,
    const float* __restrict__ bv, const float* __restrict__ rel,
    float* __restrict__ z)
{
    extern __shared__ float sm[];
    float* ks = sm;                     // KROWS x 65
    float* vs = ks + KROWS * 65;        // KROWS x 65
    float* qs = vs + KROWS * 65;        // TS x 65
    float* rs = qs + TS * 65;           // 11 x 65

    const int h  = blockIdx.y;
    const int b  = blockIdx.z;
    const int s0 = blockIdx.x * TS;
    const int tid = threadIdx.x;
    const size_t baseTok = (size_t)b * SS;
    const int hoff = h * DHEAD;

    // Load K and V window rows (clamped indices, matching jnp.clip gather)
    for (int idx = tid; idx < KROWS * (DHEAD / 4); idx += 256) {
        int i = idx >> 4;
        int d = (idx & 15) * 4;
        int t = s0 - RR + i;
        t = min(max(t, 0), SS - 1);
        const float* row = qkv + (baseTok + t) * (3 * D_MODEL);
        float4 k4 = *(const float4*)(row + D_MODEL + hoff + d);
        float4 b4 = *(const float4*)(bk + hoff + d);
        ks[i * 65 + d + 0] = k4.x + b4.x; ks[i * 65 + d + 1] = k4.y + b4.y;
        ks[i * 65 + d + 2] = k4.z + b4.z; ks[i * 65 + d + 3] = k4.w + b4.w;
        float4 v4 = *(const float4*)(row + 2 * D_MODEL + hoff + d);
        float4 c4 = *(const float4*)(bv + hoff + d);
        vs[i * 65 + d + 0] = v4.x + c4.x; vs[i * 65 + d + 1] = v4.y + c4.y;
        vs[i * 65 + d + 2] = v4.z + c4.z; vs[i * 65 + d + 3] = v4.w + c4.w;
    }
    // Load Q rows
    for (int idx = tid; idx < TS * (DHEAD / 4); idx += 256) {
        int i = idx >> 4;
        int d = (idx & 15) * 4;
        float4 q4 = *(const float4*)(qkv + (baseTok + s0 + i) * (3 * D_MODEL) + hoff + d);
        float4 b4 = *(const float4*)(bq + hoff + d);
        qs[i * 65 + d + 0] = q4.x + b4.x; qs[i * 65 + d + 1] = q4.y + b4.y;
        qs[i * 65 + d + 2] = q4.z + b4.z; qs[i * 65 + d + 3] = q4.w + b4.w;
    }
    // Load rel embeddings (11 x 64)
    for (int idx = tid; idx < 11 * (DHEAD / 4); idx += 256) {
        int r = idx >> 4;
        int d = (idx & 15) * 4;
        float4 r4 = *(const float4*)(rel + r * DHEAD + d);
        rs[r * 65 + d + 0] = r4.x; rs[r * 65 + d + 1] = r4.y;
        rs[r * 65 + d + 2] = r4.z; rs[r * 65 + d + 3] = r4.w;
    }
    __syncthreads();

    const int warp = tid >> 5;
    const int lane = tid & 31;
    const float scale = 0.125f;  // 1/sqrt(64)

    for (int qi = warp; qi < TS; qi += 8) {
        const int sq = s0 + qi;
        const float* qrow = qs + qi * 65;
        const int w0 = lane;
        const int w1 = lane + 32;
        const bool has1 = (w1 < WW);   // lanes 0..18
        int rid0 = min(max(w0 - RR, -KCLIP), KCLIP) + KCLIP;
        int rid1 = min(max(w1 - RR, -KCLIP), KCLIP) + KCLIP;
        const float* k0p = ks + (qi + w0) * 65;
        const float* k1p = ks + (qi + (has1 ? w1 : 0)) * 65;
        const float* r0p = rs + rid0 * 65;
        const float* r1p = rs + rid1 * 65;

        float a0 = 0.f, a1 = 0.f;
#pragma unroll 16
        for (int d = 0; d < DHEAD; d++) {
            float qd = qrow[d];
            a0 = fmaf(qd, k0p[d] + r0p[d], a0);
            a1 = fmaf(qd, k1p[d] + r1p[d], a1);
        }
        int j0 = sq + w0 - RR;
        int j1 = sq + w1 - RR;
        float sc0 = (j0 >= 0 && j0 < SS) ? a0 * scale : -1e30f;
        float sc1 = (has1 && j1 >= 0 && j1 < SS) ? a1 * scale : -1e30f;

        float m = fmaxf(sc0, sc1);
#pragma unroll
        for (int o = 16; o; o >>= 1) m = fmaxf(m, __shfl_xor_sync(0xffffffffu, m, o));
        float p0 = __expf(sc0 - m);
        float p1 = __expf(sc1 - m);
        float sum = p0 + p1;
#pragma unroll
        for (int o = 16; o; o >>= 1) sum += __shfl_xor_sync(0xffffffffu, sum, o);
        float inv = 1.0f / sum;
        p0 *= inv; p1 *= inv;

        float o0 = 0.f, o1 = 0.f;
#pragma unroll
        for (int w = 0; w < WW; w++) {
            float pw = __shfl_sync(0xffffffffu, (w < 32) ? p0 : p1, w & 31);
            const float* vp = vs + (qi + w) * 65;
            o0 = fmaf(pw, vp[lane], o0);
            o1 = fmaf(pw, vp[lane + 32], o1);
        }
        float* zp = z + (baseTok + sq) * D_MODEL + hoff;
        zp[lane]      = o0;
        zp[lane + 32] = o1;
    }
}

// ---------------- Elementwise epilogues ----------------
// c[i] += bias[col] + res[i]   (float4; mask4 = (N/4 - 1))
__global__ void bias_res_kernel(float* __restrict__ c, const float* __restrict__ bias,
                                const float* __restrict__ res, int mask4, int total4)
{
    int i = blockIdx.x * blockDim.x + threadIdx.x;
    if (i >= total4) return;
    float4 cv = ((float4*)c)[i];
    float4 bv = ((const float4*)bias)[i & mask4];
    float4 rv = ((const float4*)res)[i];
    cv.x += bv.x + rv.x; cv.y += bv.y + rv.y;
    cv.z += bv.z + rv.z; cv.w += bv.w + rv.w;
    ((float4*)c)[i] = cv;
}

// c[i] = relu(c[i] + bias[col])  in-place
__global__ void bias_relu_kernel(float* __restrict__ c, const float* __restrict__ bias,
                                 int mask4, int total4)
{
    int i = blockIdx.x * blockDim.x + threadIdx.x;
    if (i >= total4) return;
    float4 cv = ((float4*)c)[i];
    float4 bv = ((const float4*)bias)[i & mask4];
    cv.x = fmaxf(cv.x + bv.x, 0.f); cv.y = fmaxf(cv.y + bv.y, 0.f);
    cv.z = fmaxf(cv.z + bv.z, 0.f); cv.w = fmaxf(cv.w + bv.w, 0.f);
    ((float4*)c)[i] = cv;
}

// ---------------- LayerNorm over rows of 1024 ----------------
__global__ __launch_bounds__(256) void ln_kernel(
    const float* __restrict__ x, const float* __restrict__ g,
    const float* __restrict__ be, float* __restrict__ y)
{
    const int row = blockIdx.x;
    const int tid = threadIdx.x;
    const float4* xr = (const float4*)(x + (size_t)row * D_MODEL);
    float4 v = xr[tid];
    float s  = v.x + v.y + v.z + v.w;
    float ss = v.x * v.x + v.y * v.y + v.z * v.z + v.w * v.w;

    __shared__ float red[2][8];
#pragma unroll
    for (int o = 16; o; o >>= 1) {
        s  += __shfl_xor_sync(0xffffffffu, s, o);
        ss += __shfl_xor_sync(0xffffffffu, ss, o);
    }
    int w = tid >> 5, l = tid & 31;
    if (l == 0) { red[0][w] = s; red[1][w] = ss; }
    __syncthreads();
    if (tid == 0) {
        float ts = 0.f, tss = 0.f;
#pragma unroll
        for (int i = 0; i < 8; i++) { ts += red[0][i]; tss += red[1][i]; }
        red[0][0] = ts; red[1][0] = tss;
    }
    __syncthreads();
    s = red[0][0]; ss = red[1][0];
    const float mean = s * (1.0f / D_MODEL);
    const float var  = ss * (1.0f / D_MODEL) - mean * mean;
    const float rstd = rsqrtf(var + 1e-5f);

    float4 gg = ((const float4*)g)[tid];
    float4 bb = ((const float4*)be)[tid];
    float4 o;
    o.x = (v.x - mean) * rstd * gg.x + bb.x;
    o.y = (v.y - mean) * rstd * gg.y + bb.y;
    o.z = (v.z - mean) * rstd * gg.z + bb.z;
    o.w = (v.w - mean) * rstd * gg.w + bb.w;
    ((float4*)(y + (size_t)row * D_MODEL))[tid] = o;
}

// ---------------- Orchestration ----------------
static inline void gemm(const float* A, const float* B, float* C,
                        int M, int N, int K, int ldc)
{
    dim3 grid(N / BN, M / BM);
    gemm_tf32<<<grid, 256>>>(A, B, C, M, N, K, ldc);
}

extern "C" void kernel_launch(void* const* d_in, const int* in_sizes, int n_in,
                              void* d_out, int out_size)
{
    (void)in_sizes; (void)n_in; (void)out_size;
    const float* src   = (const float*)d_in[0];
    const float* wq    = (const float*)d_in[1];
    const float* bq    = (const float*)d_in[2];
    const float* wk    = (const float*)d_in[3];
    const float* bk    = (const float*)d_in[4];
    const float* wv    = (const float*)d_in[5];
    const float* bv    = (const float*)d_in[6];
    const float* wo    = (const float*)d_in[7];
    const float* bo    = (const float*)d_in[8];
    const float* rel   = (const float*)d_in[9];
    const float* w1    = (const float*)d_in[10];
    const float* b1    = (const float*)d_in[11];
    const float* w2    = (const float*)d_in[12];
    const float* b2    = (const float*)d_in[13];
    const float* g1    = (const float*)d_in[14];
    const float* beta1 = (const float*)d_in[15];
    const float* g2    = (const float*)d_in[16];
    const float* beta2 = (const float*)d_in[17];
    float* out = (float*)d_out;

    float *qkv, *z, *c1, *x1, *c2;
    cudaGetSymbolAddress((void**)&qkv, g_qkv);
    cudaGetSymbolAddress((void**)&z,   g_z);
    cudaGetSymbolAddress((void**)&c1,  g_c1);
    cudaGetSymbolAddress((void**)&x1,  g_x1);
    cudaGetSymbolAddress((void**)&c2,  g_c2);

    cudaFuncSetAttribute(attn_kernel, cudaFuncAttributeMaxDynamicSharedMemorySize, ATTN_SMEM);

    // 1) QKV projections (biases folded into attention load)
    gemm(src, wq, qkv + 0 * D_MODEL, NTOK, D_MODEL, D_MODEL, 3 * D_MODEL);
    gemm(src, wk, qkv + 1 * D_MODEL, NTOK, D_MODEL, D_MODEL, 3 * D_MODEL);
    gemm(src, wv, qkv + 2 * D_MODEL, NTOK, D_MODEL, D_MODEL, 3 * D_MODEL);

    // 2) Windowed relative attention -> z
    attn_kernel<<<dim3(SS / TS, NHEAD, BB), 256, ATTN_SMEM>>>(qkv, bq, bk, bv, rel, z);

    // 3) Out-proj + bias + residual(src), then LN1 -> x1
    gemm(z, wo, c1, NTOK, D_MODEL, D_MODEL, D_MODEL);
    {
        int total4 = NTOK * D_MODEL / 4;
        bias_res_kernel<<<(total4 + 255) / 256, 256>>>(c1, bo, src, D_MODEL / 4 - 1, total4);
    }
    ln_kernel<<<NTOK, 256>>>(c1, g1, beta1, x1);

    // 4) FFN: relu(x1 @ w1^T + b1) @ w2^T + b2, residual(x1), LN2 -> out
    gemm(x1, w1, c2, NTOK, DFF, D_MODEL, DFF);
    {
        int total4 = NTOK * DFF / 4;
        bias_relu_kernel<<<(total4 + 255) / 256, 256>>>(c2, b1, DFF / 4 - 1, total4);
    }
    gemm(c2, w2, c1, NTOK, D_MODEL, DFF, D_MODEL);
    {
        int total4 = NTOK * D_MODEL / 4;
        bias_res_kernel<<<(total4 + 255) / 256, 256>>>(c1, b2, x1, D_MODEL / 4 - 1, total4);
    }
    ln_kernel<<<NTOK, 256>>>(c1, g2, beta2, out);
}

// round 2
// speedup vs baseline: 1.2620x; 1.2620x over previous
#include <cuda_runtime.h>
#include <cuda_bf16.h>
#include <mma.h>
#include <cstdint>

using namespace nvcuda;

// ---------------- Problem constants ----------------
#define D_MODEL 1024
#define NHEAD   16
#define DHEAD   64
#define DFF     4096
#define BB      2
#define SS      2048
#define RR      25
#define WW      51          // 2R+1
#define KCLIP   5
#define NTOK    (BB * SS)   // 4096

// ---------------- Scratch (static device memory; no allocations) ----------------
__device__ float g_qkv[(size_t)NTOK * 3 * D_MODEL]; // Q|K|V per token, stride 3072
__device__ float g_z  [(size_t)NTOK * D_MODEL];     // attention output (pre out-proj)
__device__ float g_c1 [(size_t)NTOK * D_MODEL];     // gemm scratch
__device__ float g_x1 [(size_t)NTOK * D_MODEL];     // post-LN1 activations
__device__ float g_c2 [(size_t)NTOK * DFF];         // FFN hidden (in-place relu)

// ---------------- TF32 wmma GEMM with cp.async double buffering ----------------
// C[M,N] = A[M,K] @ B[N,K]^T ; A,B row-major (ld=K), C row-major (ldc)
#define BM 128
#define BN 128
#define BK 32
#define LDT 36   // padded shared ld (floats); 144B = 9*16B

__device__ __forceinline__ void cpasync16(void* s, const void* g) {
    uint32_t sa = (uint32_t)__cvta_generic_to_shared(s);
    asm volatile("cp.async.cg.shared.global [%0], [%1], 16;\n" :: "r"(sa), "l"(g));
}

#define GEMM_SMEM (4 * BM * LDT * 4)  // 2 stages * (A+B) * 128*36 floats = 73728 B

__global__ __launch_bounds__(256) void gemm_tf32(
    const float* __restrict__ A, const float* __restrict__ B,
    float* __restrict__ C, int M, int N, int K, int ldc)
{
    extern __shared__ float smem_dyn[];
    float* As = smem_dyn;                  // [2][BM][LDT]
    float* Bs = smem_dyn + 2 * BM * LDT;   // [2][BM][LDT]

    const int tid  = threadIdx.x;
    const int bm   = blockIdx.y * BM;
    const int bn   = blockIdx.x * BN;
    const int warp = tid >> 5;
    const int wm   = (warp & 3) * 32;   // 4 warps along M (32 rows each)
    const int wn   = (warp >> 2) * 64;  // 2 warps along N (64 cols each)

    const int r  = tid >> 3;            // 0..31 within a 256-thread pass
    const int q  = tid & 7;             // float4 quad within 32-float row chunk

    wmma::fragment<wmma::accumulator, 16, 16, 8, float> acc[2][4];
#pragma unroll
    for (int i = 0; i < 2; i++)
#pragma unroll
        for (int j = 0; j < 4; j++) wmma::fill_fragment(acc[i][j], 0.0f);

    const int niter = K / BK;

    // --- stage-load helper (as lambda via macro) ---
#define LOAD_TILE(buf, k0)                                                        \
    {                                                                             \
        _Pragma("unroll")                                                         \
        for (int t = 0; t < 4; t++) {                                             \
            int rr = r + t * 32;                                                  \
            cpasync16(&As[(size_t)(buf) * BM * LDT + rr * LDT + q * 4],           \
                      A + (size_t)(bm + rr) * K + (k0) + q * 4);                  \
            cpasync16(&Bs[(size_t)(buf) * BM * LDT + rr * LDT + q * 4],           \
                      B + (size_t)(bn + rr) * K + (k0) + q * 4);                  \
        }                                                                         \
        asm volatile("cp.async.commit_group;\n");                                 \
    }

    LOAD_TILE(0, 0);

    for (int it = 0; it < niter; it++) {
        if (it + 1 < niter) {
            LOAD_TILE((it + 1) & 1, (it + 1) * BK);
            asm volatile("cp.async.wait_group 1;\n");
        } else {
            asm volatile("cp.async.wait_group 0;\n");
        }
        __syncthreads();

        const float* Ab = As + (size_t)(it & 1) * BM * LDT;
        const float* Bb = Bs + (size_t)(it & 1) * BM * LDT;
#pragma unroll
        for (int kk = 0; kk < BK; kk += 8) {
            wmma::fragment<wmma::matrix_a, 16, 16, 8, wmma::precision::tf32, wmma::row_major> af[2];
            wmma::fragment<wmma::matrix_b, 16, 16, 8, wmma::precision::tf32, wmma::col_major> bf[4];
#pragma unroll
            for (int i = 0; i < 2; i++) {
                wmma::load_matrix_sync(af[i], Ab + (wm + i * 16) * LDT + kk, LDT);
#pragma unroll
                for (int t = 0; t < af[i].num_elements; t++)
                    af[i].x[t] = wmma::__float_to_tf32(af[i].x[t]);
            }
#pragma unroll
            for (int j = 0; j < 4; j++) {
                wmma::load_matrix_sync(bf[j], Bb + (wn + j * 16) * LDT + kk, LDT);
#pragma unroll
                for (int t = 0; t < bf[j].num_elements; t++)
                    bf[j].x[t] = wmma::__float_to_tf32(bf[j].x[t]);
            }
#pragma unroll
            for (int i = 0; i < 2; i++)
#pragma unroll
                for (int j = 0; j < 4; j++)
                    wmma::mma_sync(acc[i][j], af[i], bf[j], acc[i][j]);
        }
        __syncthreads();
    }
#undef LOAD_TILE

#pragma unroll
    for (int i = 0; i < 2; i++)
#pragma unroll
        for (int j = 0; j < 4; j++)
            wmma::store_matrix_sync(
                &C[(size_t)(bm + wm + i * 16) * ldc + bn + wn + j * 16],
                acc[i][j], ldc, wmma::mem_row_major);
}

// ---------------- Windowed relative attention ----------------
#define TS 64
#define KROWS (TS + 2 * RR)   // 114
#define ATTN_SMEM (((KROWS * 65) * 2 + TS * 65 + 11 * 65) * 4)

__global__ __launch_bounds__(256) void attn_kernel(
    const float* __restrict__ qkv,
    const float* __restrict__ bq, const float* __restrict__ bk,
    const float* __restrict__ bv, const float* __restrict__ rel,
    float* __restrict__ z)
{
    extern __shared__ float sm[];
    float* ks = sm;                     // KROWS x 65
    float* vs = ks + KROWS * 65;        // KROWS x 65
    float* qs = vs + KROWS * 65;        // TS x 65
    float* rs = qs + TS * 65;           // 11 x 65

    const int h  = blockIdx.y;
    const int b  = blockIdx.z;
    const int s0 = blockIdx.x * TS;
    const int tid = threadIdx.x;
    const size_t baseTok = (size_t)b * SS;
    const int hoff = h * DHEAD;

    for (int idx = tid; idx < KROWS * (DHEAD / 4); idx += 256) {
        int i = idx >> 4;
        int d = (idx & 15) * 4;
        int t = s0 - RR + i;
        t = min(max(t, 0), SS - 1);
        const float* row = qkv + (baseTok + t) * (3 * D_MODEL);
        float4 k4 = *(const float4*)(row + D_MODEL + hoff + d);
        float4 b4 = *(const float4*)(bk + hoff + d);
        ks[i * 65 + d + 0] = k4.x + b4.x; ks[i * 65 + d + 1] = k4.y + b4.y;
        ks[i * 65 + d + 2] = k4.z + b4.z; ks[i * 65 + d + 3] = k4.w + b4.w;
        float4 v4 = *(const float4*)(row + 2 * D_MODEL + hoff + d);
        float4 c4 = *(const float4*)(bv + hoff + d);
        vs[i * 65 + d + 0] = v4.x + c4.x; vs[i * 65 + d + 1] = v4.y + c4.y;
        vs[i * 65 + d + 2] = v4.z + c4.z; vs[i * 65 + d + 3] = v4.w + c4.w;
    }
    for (int idx = tid; idx < TS * (DHEAD / 4); idx += 256) {
        int i = idx >> 4;
        int d = (idx & 15) * 4;
        float4 q4 = *(const float4*)(qkv + (baseTok + s0 + i) * (3 * D_MODEL) + hoff + d);
        float4 b4 = *(const float4*)(bq + hoff + d);
        qs[i * 65 + d + 0] = q4.x + b4.x; qs[i * 65 + d + 1] = q4.y + b4.y;
        qs[i * 65 + d + 2] = q4.z + b4.z; qs[i * 65 + d + 3] = q4.w + b4.w;
    }
    for (int idx = tid; idx < 11 * (DHEAD / 4); idx += 256) {
        int rr = idx >> 4;
        int d = (idx & 15) * 4;
        float4 r4 = *(const float4*)(rel + rr * DHEAD + d);
        rs[rr * 65 + d + 0] = r4.x; rs[rr * 65 + d + 1] = r4.y;
        rs[rr * 65 + d + 2] = r4.z; rs[rr * 65 + d + 3] = r4.w;
    }
    __syncthreads();

    const int warp = tid >> 5;
    const int lane = tid & 31;
    const float scale = 0.125f;

    for (int qi = warp; qi < TS; qi += 8) {
        const int sq = s0 + qi;
        const float* qrow = qs + qi * 65;
        const int w0 = lane;
        const int w1 = lane + 32;
        const bool has1 = (w1 < WW);
        int rid0 = min(max(w0 - RR, -KCLIP), KCLIP) + KCLIP;
        int rid1 = min(max(w1 - RR, -KCLIP), KCLIP) + KCLIP;
        const float* k0p = ks + (qi + w0) * 65;
        const float* k1p = ks + (qi + (has1 ? w1 : 0)) * 65;
        const float* r0p = rs + rid0 * 65;
        const float* r1p = rs + rid1 * 65;

        float a0 = 0.f, a1 = 0.f;
#pragma unroll 16
        for (int d = 0; d < DHEAD; d++) {
            float qd = qrow[d];
            a0 = fmaf(qd, k0p[d] + r0p[d], a0);
            a1 = fmaf(qd, k1p[d] + r1p[d], a1);
        }
        int j0 = sq + w0 - RR;
        int j1 = sq + w1 - RR;
        float sc0 = (j0 >= 0 && j0 < SS) ? a0 * scale : -1e30f;
        float sc1 = (has1 && j1 >= 0 && j1 < SS) ? a1 * scale : -1e30f;

        float m = fmaxf(sc0, sc1);
#pragma unroll
        for (int o = 16; o; o >>= 1) m = fmaxf(m, __shfl_xor_sync(0xffffffffu, m, o));
        float p0 = __expf(sc0 - m);
        float p1 = __expf(sc1 - m);
        float sum = p0 + p1;
#pragma unroll
        for (int o = 16; o; o >>= 1) sum += __shfl_xor_sync(0xffffffffu, sum, o);
        float inv = 1.0f / sum;
        p0 *= inv; p1 *= inv;

        float o0 = 0.f, o1 = 0.f;
#pragma unroll
        for (int w = 0; w < WW; w++) {
            float pw = __shfl_sync(0xffffffffu, (w < 32) ? p0 : p1, w & 31);
            const float* vp = vs + (qi + w) * 65;
            o0 = fmaf(pw, vp[lane], o0);
            o1 = fmaf(pw, vp[lane + 32], o1);
        }
        float* zp = z + (baseTok + sq) * D_MODEL + hoff;
        zp[lane]      = o0;
        zp[lane + 32] = o1;
    }
}

// ---------------- Elementwise: relu(c + bias) in-place ----------------
__global__ void bias_relu_kernel(float* __restrict__ c, const float* __restrict__ bias,
                                 int mask4, int total4)
{
    int i = blockIdx.x * blockDim.x + threadIdx.x;
    if (i >= total4) return;
    float4 cv = ((float4*)c)[i];
    float4 bv = ((const float4*)bias)[i & mask4];
    cv.x = fmaxf(cv.x + bv.x, 0.f); cv.y = fmaxf(cv.y + bv.y, 0.f);
    cv.z = fmaxf(cv.z + bv.z, 0.f); cv.w = fmaxf(cv.w + bv.w, 0.f);
    ((float4*)c)[i] = cv;
}

// ---------------- Fused bias + residual + LayerNorm (rows of 1024) ----------------
__global__ __launch_bounds__(256) void ln_fused_kernel(
    const float* __restrict__ c, const float* __restrict__ bias,
    const float* __restrict__ res, const float* __restrict__ g,
    const float* __restrict__ be, float* __restrict__ y)
{
    const int row = blockIdx.x;
    const int tid = threadIdx.x;
    float4 v = ((const float4*)(c + (size_t)row * D_MODEL))[tid];
    float4 bb4 = ((const float4*)bias)[tid];
    float4 rr4 = ((const float4*)(res + (size_t)row * D_MODEL))[tid];
    v.x += bb4.x + rr4.x; v.y += bb4.y + rr4.y;
    v.z += bb4.z + rr4.z; v.w += bb4.w + rr4.w;

    float s  = v.x + v.y + v.z + v.w;
    float ss = v.x * v.x + v.y * v.y + v.z * v.z + v.w * v.w;

    __shared__ float red[2][8];
#pragma unroll
    for (int o = 16; o; o >>= 1) {
        s  += __shfl_xor_sync(0xffffffffu, s, o);
        ss += __shfl_xor_sync(0xffffffffu, ss, o);
    }
    int w = tid >> 5, l = tid & 31;
    if (l == 0) { red[0][w] = s; red[1][w] = ss; }
    __syncthreads();
    if (tid == 0) {
        float ts = 0.f, tss = 0.f;
#pragma unroll
        for (int i = 0; i < 8; i++) { ts += red[0][i]; tss += red[1][i]; }
        red[0][0] = ts; red[1][0] = tss;
    }
    __syncthreads();
    s = red[0][0]; ss = red[1][0];
    const float mean = s * (1.0f / D_MODEL);
    const float var  = ss * (1.0f / D_MODEL) - mean * mean;
    const float rstd = rsqrtf(var + 1e-5f);

    float4 gg = ((const float4*)g)[tid];
    float4 be4 = ((const float4*)be)[tid];
    float4 o;
    o.x = (v.x - mean) * rstd * gg.x + be4.x;
    o.y = (v.y - mean) * rstd * gg.y + be4.y;
    o.z = (v.z - mean) * rstd * gg.z + be4.z;
    o.w = (v.w - mean) * rstd * gg.w + be4.w;
    ((float4*)(y + (size_t)row * D_MODEL))[tid] = o;
}

// ---------------- Orchestration ----------------
static inline void gemm(const float* A, const float* B, float* C,
                        int M, int N, int K, int ldc)
{
    dim3 grid(N / BN, M / BM);
    gemm_tf32<<<grid, 256, GEMM_SMEM>>>(A, B, C, M, N, K, ldc);
}

extern "C" void kernel_launch(void* const* d_in, const int* in_sizes, int n_in,
                              void* d_out, int out_size)
{
    (void)in_sizes; (void)n_in; (void)out_size;
    const float* src   = (const float*)d_in[0];
    const float* wq    = (const float*)d_in[1];
    const float* bq    = (const float*)d_in[2];
    const float* wk    = (const float*)d_in[3];
    const float* bk    = (const float*)d_in[4];
    const float* wv    = (const float*)d_in[5];
    const float* bv    = (const float*)d_in[6];
    const float* wo    = (const float*)d_in[7];
    const float* bo    = (const float*)d_in[8];
    const float* rel   = (const float*)d_in[9];
    const float* w1    = (const float*)d_in[10];
    const float* b1    = (const float*)d_in[11];
    const float* w2    = (const float*)d_in[12];
    const float* b2    = (const float*)d_in[13];
    const float* g1    = (const float*)d_in[14];
    const float* beta1 = (const float*)d_in[15];
    const float* g2    = (const float*)d_in[16];
    const float* beta2 = (const float*)d_in[17];
    float* out = (float*)d_out;

    float *qkv, *z, *c1, *x1, *c2;
    cudaGetSymbolAddress((void**)&qkv, g_qkv);
    cudaGetSymbolAddress((void**)&z,   g_z);
    cudaGetSymbolAddress((void**)&c1,  g_c1);
    cudaGetSymbolAddress((void**)&x1,  g_x1);
    cudaGetSymbolAddress((void**)&c2,  g_c2);

    cudaFuncSetAttribute(gemm_tf32, cudaFuncAttributeMaxDynamicSharedMemorySize, GEMM_SMEM);
    cudaFuncSetAttribute(attn_kernel, cudaFuncAttributeMaxDynamicSharedMemorySize, ATTN_SMEM);

    // 1) QKV projections (biases folded into attention load)
    gemm(src, wq, qkv + 0 * D_MODEL, NTOK, D_MODEL, D_MODEL, 3 * D_MODEL);
    gemm(src, wk, qkv + 1 * D_MODEL, NTOK, D_MODEL, D_MODEL, 3 * D_MODEL);
    gemm(src, wv, qkv + 2 * D_MODEL, NTOK, D_MODEL, D_MODEL, 3 * D_MODEL);

    // 2) Windowed relative attention -> z
    attn_kernel<<<dim3(SS / TS, NHEAD, BB), 256, ATTN_SMEM>>>(qkv, bq, bk, bv, rel, z);

    // 3) Out-proj, then fused bias+residual+LN1 -> x1
    gemm(z, wo, c1, NTOK, D_MODEL, D_MODEL, D_MODEL);
    ln_fused_kernel<<<NTOK, 256>>>(c1, bo, src, g1, beta1, x1);

    // 4) FFN
    gemm(x1, w1, c2, NTOK, DFF, D_MODEL, DFF);
    {
        int total4 = NTOK * DFF / 4;
        bias_relu_kernel<<<(total4 + 255) / 256, 256>>>(c2, b1, DFF / 4 - 1, total4);
    }
    gemm(c2, w2, c1, NTOK, D_MODEL, DFF, D_MODEL);
    ln_fused_kernel<<<NTOK, 256>>>(c1, b2, x1, g2, beta2, out);
}

// round 4
// speedup vs baseline: 3.4212x; 2.7110x over previous
#include <cuda_runtime.h>
#include <cuda_fp16.h>
#include <cstdint>

// ---------------- Problem constants ----------------
#define D_MODEL 1024
#define NHEAD   16
#define DHEAD   64
#define DFF     4096
#define BB      2
#define SS      2048
#define RR      25
#define WW      51
#define KCLIP   5
#define NTOK    (BB * SS)

// ---------------- Scratch ----------------
__device__ float  g_qkv[(size_t)NTOK * 3 * D_MODEL];   // fp32 Q|K|V (ldc=3072)
__device__ float  g_c1 [(size_t)NTOK * D_MODEL];
__device__ float  g_x1 [(size_t)NTOK * D_MODEL];
__device__ __half g_srch[(size_t)NTOK * D_MODEL];
__device__ __half g_zh  [(size_t)NTOK * D_MODEL];
__device__ __half g_x1h [(size_t)NTOK * D_MODEL];
__device__ __half g_c2h [(size_t)NTOK * DFF];
__device__ __half g_wqh[(size_t)D_MODEL * D_MODEL];
__device__ __half g_wkh[(size_t)D_MODEL * D_MODEL];
__device__ __half g_wvh[(size_t)D_MODEL * D_MODEL];
__device__ __half g_woh[(size_t)D_MODEL * D_MODEL];
__device__ __half g_w1h[(size_t)DFF * D_MODEL];
__device__ __half g_w2h[(size_t)D_MODEL * DFF];

// ---------------- helpers ----------------
__device__ __forceinline__ uint32_t smem_u32(const void* p) {
    uint32_t a;
    asm("{ .reg .u64 t; cvta.to.shared.u64 t, %1; cvt.u32.u64 %0, t; }" : "=r"(a) : "l"(p));
    return a;
}
__device__ __forceinline__ void cpasync16(uint32_t s, const void* g) {
    asm volatile("cp.async.cg.shared.global [%0], [%1], 16;\n" :: "r"(s), "l"(g));
}
__device__ __forceinline__ void ldm_x4(uint32_t& r0, uint32_t& r1, uint32_t& r2, uint32_t& r3,
                                       uint32_t addr) {
    asm volatile("ldmatrix.sync.aligned.m8n8.x4.shared.b16 {%0,%1,%2,%3}, [%4];"
                 : "=r"(r0), "=r"(r1), "=r"(r2), "=r"(r3) : "r"(addr));
}
__device__ __forceinline__ void mma16816(float* d, const uint32_t* a, uint32_t b0, uint32_t b1) {
    asm volatile("mma.sync.aligned.m16n8k16.row.col.f32.f16.f16.f32 "
                 "{%0,%1,%2,%3}, {%4,%5,%6,%7}, {%8,%9}, {%0,%1,%2,%3};"
                 : "+f"(d[0]), "+f"(d[1]), "+f"(d[2]), "+f"(d[3])
                 : "r"(a[0]), "r"(a[1]), "r"(a[2]), "r"(a[3]), "r"(b0), "r"(b1));
}

// ---------------- fp16 GEMM: C[M,N] = A[M,K] @ B[N,K]^T ----------------
// A,B half row-major (ld=K). mode 0: store fp32 Cf. mode 1: bias+relu -> half Ch.
// CTA 128x128, BK=32, 3 stages; tile rows padded to 80B (5x16B, conflict-free).
#define ST_A 10240              // 128 rows * 80B
#define ST_STAGE 20480          // A + B
#define HGEMM_SMEM (3 * ST_STAGE)

__global__ __launch_bounds__(256, 2) void hgemm(
    const __half* __restrict__ A, const __half* __restrict__ B,
    float* __restrict__ Cf, __half* __restrict__ Ch,
    int M, int N, int K, int ldc, int mode, const float* __restrict__ bias)
{
    extern __shared__ char smem[];
    const uint32_t sb = smem_u32(smem);
    const int tid = threadIdx.x;
    const int bm = blockIdx.y * 128;
    const int bn = blockIdx.x * 128;
    const int niter = K >> 5;

    // producer mapping: each thread copies 2 A-chunks + 2 B-chunks (16B each)
    const int pr = tid >> 1;            // row 0..127
    const int pc = (tid & 1) * 2;       // chunk base 0 or 2
    const __half* Agp = A + (size_t)(bm + pr) * K + pc * 8;
    const __half* Bgp = B + (size_t)(bn + pr) * K + pc * 8;
    const uint32_t sOff = (uint32_t)(pr * 5 + pc) * 16;

#define LOADSTAGE(s, it) do {                                     \
        uint32_t as_ = sb + (s) * ST_STAGE + sOff;                \
        const __half* ag_ = Agp + (size_t)(it) * 32;              \
        const __half* bg_ = Bgp + (size_t)(it) * 32;              \
        cpasync16(as_,            ag_);                           \
        cpasync16(as_ + 16,       ag_ + 8);                       \
        cpasync16(as_ + ST_A,     bg_);                           \
        cpasync16(as_ + ST_A + 16, bg_ + 8);                      \
    } while (0)
#define COMMIT() asm volatile("cp.async.commit_group;\n")

    const int warp = tid >> 5;
    const int lane = tid & 31;
    const int wm = (warp & 1) * 64;     // 2 warps along M
    const int wn = (warp >> 1) * 32;    // 4 warps along N
    const int grp = lane >> 3;
    const int lr  = lane & 7;
    const int lrow = (grp & 1) * 8 + lr;   // row within 16-row tile
    const int lchk = grp >> 1;             // k-half chunk

    float acc[4][4][4];
#pragma unroll
    for (int i = 0; i < 4; i++)
#pragma unroll
        for (int j = 0; j < 4; j++)
#pragma unroll
            for (int t = 0; t < 4; t++) acc[i][j][t] = 0.f;

    LOADSTAGE(0, 0); COMMIT();
    LOADSTAGE(1, 1); COMMIT();

    int stage = 0;
    for (int it = 0; it < niter; it++) {
        if (it + 2 < niter) LOADSTAGE((it + 2) % 3, it + 2);
        COMMIT();
        asm volatile("cp.async.wait_group 2;\n");
        __syncthreads();

        const uint32_t aS = sb + stage * ST_STAGE;
        const uint32_t bS = aS + ST_A;
#pragma unroll
        for (int ks = 0; ks < 2; ks++) {
            uint32_t af[4][4], bf[2][4];
#pragma unroll
            for (int mt = 0; mt < 4; mt++) {
                uint32_t addr = aS + (uint32_t)(((wm + mt * 16 + lrow) * 5 + ks * 2 + lchk) * 16);
                ldm_x4(af[mt][0], af[mt][1], af[mt][2], af[mt][3], addr);
            }
#pragma unroll
            for (int nc = 0; nc < 2; nc++) {
                uint32_t addr = bS + (uint32_t)(((wn + nc * 16 + lrow) * 5 + ks * 2 + lchk) * 16);
                ldm_x4(bf[nc][0], bf[nc][1], bf[nc][2], bf[nc][3], addr);
            }
#pragma unroll
            for (int mt = 0; mt < 4; mt++)
#pragma unroll
                for (int nj = 0; nj < 4; nj++) {
                    int nc = nj >> 1, sub = nj & 1;
                    mma16816(acc[mt][nj], af[mt], bf[nc][sub], bf[nc][sub + 2]);
                }
        }
        __syncthreads();
        stage = (stage + 1) == 3 ? 0 : stage + 1;
    }
#undef LOADSTAGE
#undef COMMIT

    // epilogue
    const int qrow = lane >> 2;
    const int qcol = (lane & 3) * 2;
#pragma unroll
    for (int mt = 0; mt < 4; mt++) {
        const int row0 = bm + wm + mt * 16 + qrow;
#pragma unroll
        for (int nj = 0; nj < 4; nj++) {
            const int col = bn + wn + nj * 8 + qcol;
            if (mode == 0) {
                *(float2*)(Cf + (size_t)row0 * ldc + col) =
                    make_float2(acc[mt][nj][0], acc[mt][nj][1]);
                *(float2*)(Cf + (size_t)(row0 + 8) * ldc + col) =
                    make_float2(acc[mt][nj][2], acc[mt][nj][3]);
            } else {
                float b0 = bias[col], b1 = bias[col + 1];
                __half2 h0 = __floats2half2_rn(fmaxf(acc[mt][nj][0] + b0, 0.f),
                                               fmaxf(acc[mt][nj][1] + b1, 0.f));
                __half2 h1 = __floats2half2_rn(fmaxf(acc[mt][nj][2] + b0, 0.f),
                                               fmaxf(acc[mt][nj][3] + b1, 0.f));
                *(__half2*)(Ch + (size_t)row0 * ldc + col) = h0;
                *(__half2*)(Ch + (size_t)(row0 + 8) * ldc + col) = h1;
            }
        }
    }
}

// ---------------- float -> half convert ----------------
__global__ void f2h_kernel(const float* __restrict__ x, __half* __restrict__ y, int n4)
{
    int i = blockIdx.x * blockDim.x + threadIdx.x;
    if (i >= n4) return;
    float4 v = ((const float4*)x)[i];
    ((__half2*)y)[i * 2 + 0] = __floats2half2_rn(v.x, v.y);
    ((__half2*)y)[i * 2 + 1] = __floats2half2_rn(v.z, v.w);
}

// ---------------- Windowed relative attention (q·rel hoisted; half z out) ----------------
#define TS 64
#define KROWS (TS + 2 * RR)
#define ATTN_SMEM (((KROWS * 65) * 2 + TS * 65 + 11 * 65) * 4)

__global__ __launch_bounds__(256) void attn_kernel(
    const float* __restrict__ qkv,
    const float* __restrict__ bq, const float* __restrict__ bk,
    const float* __restrict__ bv, const float* __restrict__ rel,
    __half* __restrict__ zh)
{
    extern __shared__ float sm[];
    float* ks = sm;
    float* vs = ks + KROWS * 65;
    float* qs = vs + KROWS * 65;
    float* rs = qs + TS * 65;

    const int h  = blockIdx.y;
    const int b  = blockIdx.z;
    const int s0 = blockIdx.x * TS;
    const int tid = threadIdx.x;
    const size_t baseTok = (size_t)b * SS;
    const int hoff = h * DHEAD;

    for (int idx = tid; idx < KROWS * (DHEAD / 4); idx += 256) {
        int i = idx >> 4;
        int d = (idx & 15) * 4;
        int t = s0 - RR + i;
        t = min(max(t, 0), SS - 1);
        const float* row = qkv + (baseTok + t) * (3 * D_MODEL);
        float4 k4 = *(const float4*)(row + D_MODEL + hoff + d);
        float4 b4 = *(const float4*)(bk + hoff + d);
        ks[i * 65 + d + 0] = k4.x + b4.x; ks[i * 65 + d + 1] = k4.y + b4.y;
        ks[i * 65 + d + 2] = k4.z + b4.z; ks[i * 65 + d + 3] = k4.w + b4.w;
        float4 v4 = *(const float4*)(row + 2 * D_MODEL + hoff + d);
        float4 c4 = *(const float4*)(bv + hoff + d);
        vs[i * 65 + d + 0] = v4.x + c4.x; vs[i * 65 + d + 1] = v4.y + c4.y;
        vs[i * 65 + d + 2] = v4.z + c4.z; vs[i * 65 + d + 3] = v4.w + c4.w;
    }
    for (int idx = tid; idx < TS * (DHEAD / 4); idx += 256) {
        int i = idx >> 4;
        int d = (idx & 15) * 4;
        float4 q4 = *(const float4*)(qkv + (baseTok + s0 + i) * (3 * D_MODEL) + hoff + d);
        float4 b4 = *(const float4*)(bq + hoff + d);
        qs[i * 65 + d + 0] = q4.x + b4.x; qs[i * 65 + d + 1] = q4.y + b4.y;
        qs[i * 65 + d + 2] = q4.z + b4.z; qs[i * 65 + d + 3] = q4.w + b4.w;
    }
    for (int idx = tid; idx < 11 * (DHEAD / 4); idx += 256) {
        int rr = idx >> 4;
        int d = (idx & 15) * 4;
        float4 r4 = *(const float4*)(rel + rr * DHEAD + d);
        rs[rr * 65 + d + 0] = r4.x; rs[rr * 65 + d + 1] = r4.y;
        rs[rr * 65 + d + 2] = r4.z; rs[rr * 65 + d + 3] = r4.w;
    }
    __syncthreads();

    const int warp = tid >> 5;
    const int lane = tid & 31;
    const float scale = 0.125f;

    for (int qi = warp; qi < TS; qi += 8) {
        const int sq = s0 + qi;
        const float* qrow = qs + qi * 65;

        // hoisted q . rel[rid] for the 11 clipped rel ids (lanes 0..10 compute)
        float qr = 0.f;
        if (lane < 11) {
            const float* rp = rs + lane * 65;
#pragma unroll 16
            for (int d = 0; d < DHEAD; d++) qr = fmaf(qrow[d], rp[d], qr);
        }

        const int w0 = lane;
        const int w1 = lane + 32;
        const bool has1 = (w1 < WW);
        int rid0 = min(max(w0 - RR, -KCLIP), KCLIP) + KCLIP;
        int rid1 = min(max(w1 - RR, -KCLIP), KCLIP) + KCLIP;
        float qr0 = __shfl_sync(0xffffffffu, qr, rid0);
        float qr1 = __shfl_sync(0xffffffffu, qr, rid1);
        const float* k0p = ks + (qi + w0) * 65;
        const float* k1p = ks + (qi + (has1 ? w1 : 0)) * 65;

        float a0 = 0.f, a1 = 0.f;
#pragma unroll 16
        for (int d = 0; d < DHEAD; d++) {
            float qd = qrow[d];
            a0 = fmaf(qd, k0p[d], a0);
            a1 = fmaf(qd, k1p[d], a1);
        }
        a0 += qr0;
        a1 += qr1;
        int j0 = sq + w0 - RR;
        int j1 = sq + w1 - RR;
        float sc0 = (j0 >= 0 && j0 < SS) ? a0 * scale : -1e30f;
        float sc1 = (has1 && j1 >= 0 && j1 < SS) ? a1 * scale : -1e30f;

        float m = fmaxf(sc0, sc1);
#pragma unroll
        for (int o = 16; o; o >>= 1) m = fmaxf(m, __shfl_xor_sync(0xffffffffu, m, o));
        float p0 = __expf(sc0 - m);
        float p1 = __expf(sc1 - m);
        float sum = p0 + p1;
#pragma unroll
        for (int o = 16; o; o >>= 1) sum += __shfl_xor_sync(0xffffffffu, sum, o);
        float inv = 1.0f / sum;
        p0 *= inv; p1 *= inv;

        float o0 = 0.f, o1 = 0.f;
#pragma unroll
        for (int w = 0; w < WW; w++) {
            float pw = __shfl_sync(0xffffffffu, (w < 32) ? p0 : p1, w & 31);
            const float* vp = vs + (qi + w) * 65;
            o0 = fmaf(pw, vp[lane], o0);
            o1 = fmaf(pw, vp[lane + 32], o1);
        }
        __half* zp = zh + (baseTok + sq) * D_MODEL + hoff;
        zp[lane]      = __float2half(o0);
        zp[lane + 32] = __float2half(o1);
    }
}

// ---------------- Fused bias + residual + LayerNorm (dual store) ----------------
__global__ __launch_bounds__(256) void ln_fused_kernel(
    const float* __restrict__ c, const float* __restrict__ bias,
    const float* __restrict__ res, const float* __restrict__ g,
    const float* __restrict__ be, float* __restrict__ y, __half* __restrict__ yh)
{
    const int row = blockIdx.x;
    const int tid = threadIdx.x;
    float4 v = ((const float4*)(c + (size_t)row * D_MODEL))[tid];
    float4 bb4 = ((const float4*)bias)[tid];
    float4 rr4 = ((const float4*)(res + (size_t)row * D_MODEL))[tid];
    v.x += bb4.x + rr4.x; v.y += bb4.y + rr4.y;
    v.z += bb4.z + rr4.z; v.w += bb4.w + rr4.w;

    float s  = v.x + v.y + v.z + v.w;
    float ss = v.x * v.x + v.y * v.y + v.z * v.z + v.w * v.w;

    __shared__ float red[2][8];
#pragma unroll
    for (int o = 16; o; o >>= 1) {
        s  += __shfl_xor_sync(0xffffffffu, s, o);
        ss += __shfl_xor_sync(0xffffffffu, ss, o);
    }
    int w = tid >> 5, l = tid & 31;
    if (l == 0) { red[0][w] = s; red[1][w] = ss; }
    __syncthreads();
    if (tid == 0) {
        float ts = 0.f, tss = 0.f;
#pragma unroll
        for (int i = 0; i < 8; i++) { ts += red[0][i]; tss += red[1][i]; }
        red[0][0] = ts; red[1][0] = tss;
    }
    __syncthreads();
    s = red[0][0]; ss = red[1][0];
    const float mean = s * (1.0f / D_MODEL);
    const float var  = ss * (1.0f / D_MODEL) - mean * mean;
    const float rstd = rsqrtf(var + 1e-5f);

    float4 gg = ((const float4*)g)[tid];
    float4 be4 = ((const float4*)be)[tid];
    float4 o;
    o.x = (v.x - mean) * rstd * gg.x + be4.x;
    o.y = (v.y - mean) * rstd * gg.y + be4.y;
    o.z = (v.z - mean) * rstd * gg.z + be4.z;
    o.w = (v.w - mean) * rstd * gg.w + be4.w;
    ((float4*)(y + (size_t)row * D_MODEL))[tid] = o;
    if (yh) {
        ((__half2*)(yh + (size_t)row * D_MODEL))[tid * 2 + 0] = __floats2half2_rn(o.x, o.y);
        ((__half2*)(yh + (size_t)row * D_MODEL))[tid * 2 + 1] = __floats2half2_rn(o.z, o.w);
    }
}

// ---------------- Orchestration ----------------
static inline void hgemm_go(const __half* A, const __half* B, float* Cf, __half* Ch,
                            int M, int N, int K, int ldc, int mode, const float* bias)
{
    dim3 grid(N / 128, M / 128);
    hgemm<<<grid, 256, HGEMM_SMEM>>>(A, B, Cf, Ch, M, N, K, ldc, mode, bias);
}
static inline void f2h(const float* x, __half* y, size_t n)
{
    int n4 = (int)(n / 4);
    f2h_kernel<<<(n4 + 255) / 256, 256>>>(x, y, n4);
}

extern "C" void kernel_launch(void* const* d_in, const int* in_sizes, int n_in,
                              void* d_out, int out_size)
{
    (void)in_sizes; (void)n_in; (void)out_size;
    const float* src   = (const float*)d_in[0];
    const float* wq    = (const float*)d_in[1];
    const float* bq    = (const float*)d_in[2];
    const float* wk    = (const float*)d_in[3];
    const float* bk    = (const float*)d_in[4];
    const float* wv    = (const float*)d_in[5];
    const float* bv    = (const float*)d_in[6];
    const float* wo    = (const float*)d_in[7];
    const float* bo    = (const float*)d_in[8];
    const float* rel   = (const float*)d_in[9];
    const float* w1    = (const float*)d_in[10];
    const float* b1    = (const float*)d_in[11];
    const float* w2    = (const float*)d_in[12];
    const float* b2    = (const float*)d_in[13];
    const float* g1    = (const float*)d_in[14];
    const float* beta1 = (const float*)d_in[15];
    const float* g2    = (const float*)d_in[16];
    const float* beta2 = (const float*)d_in[17];
    float* out = (float*)d_out;

    float *qkv, *c1, *x1;
    __half *srch, *zhp, *x1h, *c2h, *wqh, *wkh, *wvh, *woh, *w1h, *w2h;
    cudaGetSymbolAddress((void**)&qkv,  g_qkv);
    cudaGetSymbolAddress((void**)&c1,   g_c1);
    cudaGetSymbolAddress((void**)&x1,   g_x1);
    cudaGetSymbolAddress((void**)&srch, g_srch);
    cudaGetSymbolAddress((void**)&zhp,  g_zh);
    cudaGetSymbolAddress((void**)&x1h,  g_x1h);
    cudaGetSymbolAddress((void**)&c2h,  g_c2h);
    cudaGetSymbolAddress((void**)&wqh,  g_wqh);
    cudaGetSymbolAddress((void**)&wkh,  g_wkh);
    cudaGetSymbolAddress((void**)&wvh,  g_wvh);
    cudaGetSymbolAddress((void**)&woh,  g_woh);
    cudaGetSymbolAddress((void**)&w1h,  g_w1h);
    cudaGetSymbolAddress((void**)&w2h,  g_w2h);

    cudaFuncSetAttribute(hgemm, cudaFuncAttributeMaxDynamicSharedMemorySize, HGEMM_SMEM);
    cudaFuncSetAttribute(attn_kernel, cudaFuncAttributeMaxDynamicSharedMemorySize, ATTN_SMEM);

    // 0) fp32 -> fp16 operand conversion
    f2h(src, srch, (size_t)NTOK * D_MODEL);
    f2h(wq, wqh, (size_t)D_MODEL * D_MODEL);
    f2h(wk, wkh, (size_t)D_MODEL * D_MODEL);
    f2h(wv, wvh, (size_t)D_MODEL * D_MODEL);
    f2h(wo, woh, (size_t)D_MODEL * D_MODEL);
    f2h(w1, w1h, (size_t)DFF * D_MODEL);
    f2h(w2, w2h, (size_t)D_MODEL * DFF);

    // 1) QKV projections -> fp32 qkv (ldc 3072); biases folded into attention
    hgemm_go(srch, wqh, qkv + 0 * D_MODEL, nullptr, NTOK, D_MODEL, D_MODEL, 3 * D_MODEL, 0, nullptr);
    hgemm_go(srch, wkh, qkv + 1 * D_MODEL, nullptr, NTOK, D_MODEL, D_MODEL, 3 * D_MODEL, 0, nullptr);
    hgemm_go(srch, wvh, qkv + 2 * D_MODEL, nullptr, NTOK, D_MODEL, D_MODEL, 3 * D_MODEL, 0, nullptr);

    // 2) attention -> z (half)
    attn_kernel<<<dim3(SS / TS, NHEAD, BB), 256, ATTN_SMEM>>>(qkv, bq, bk, bv, rel, zhp);

    // 3) out-proj -> c1 fp32; fused bias+residual+LN1 -> x1 (fp32 + half)
    hgemm_go(zhp, woh, c1, nullptr, NTOK, D_MODEL, D_MODEL, D_MODEL, 0, nullptr);
    ln_fused_kernel<<<NTOK, 256>>>(c1, bo, src, g1, beta1, x1, x1h);

    // 4) FFN1: bias+relu fused, half output
    hgemm_go(x1h, w1h, nullptr, c2h, NTOK, DFF, D_MODEL, DFF, 1, b1);
    // 5) FFN2 -> c1 fp32; fused bias+residual+LN2 -> out
    hgemm_go(c2h, w2h, c1, nullptr, NTOK, D_MODEL, DFF, D_MODEL, 0, nullptr);
    ln_fused_kernel<<<NTOK, 256>>>(c1, b2, x1, g2, beta2, out, nullptr);
}